// round 1
// baseline (speedup 1.0000x reference)
#include <cuda_runtime.h>

// Shapes fixed by the problem: L=1024, D=640, K=32, M=64
#define LMAX 1024
#define MM   64
#define KK   32
#define KP   36   // padded e_scalar length (etype, pij, 32 rbf, 2 zero pad)

// scratch: node projection + bias, 1024 x 64 fp32 = 256 KB (L2-resident)
__device__ float g_nb[LMAX * MM];

// ---------------------------------------------------------------------------
// Kernel 1: nb[j,m] = sum_d S[j,d] * W_node[d,m] + b_edge[m]
// block = 256 threads = 4 j-rows x 64 m;  grid = L/4
// ---------------------------------------------------------------------------
__global__ void __launch_bounds__(256) node_proj_kernel(
    const float* __restrict__ S,
    const float* __restrict__ W_node,
    const float* __restrict__ b_edge,
    int L, int D)
{
    int m  = threadIdx.x & 63;
    int jr = threadIdx.x >> 6;           // 0..3
    int j  = blockIdx.x * 4 + jr;

    __shared__ float sS[4][64];
    __shared__ float sW[64][65];

    float acc = 0.f;
    for (int d0 = 0; d0 < D; d0 += 64) {
        sS[jr][m] = S[(size_t)j * D + d0 + m];
        #pragma unroll
        for (int r = 0; r < 64; r += 4)
            sW[r + jr][m] = W_node[(size_t)(d0 + r + jr) * MM + m];
        __syncthreads();
        #pragma unroll
        for (int d = 0; d < 64; d++)
            acc = fmaf(sS[jr][d], sW[d][m], acc);
        __syncthreads();
    }
    g_nb[j * MM + m] = acc + b_edge[m];
}

// ---------------------------------------------------------------------------
// Kernel 2: per destination row i — compact active edges, fused
// rbf -> e_scalar@W_edge -> relu -> dot w_out -> sigmoid -> gated vec accum.
// block = 256 threads, grid = L
// ---------------------------------------------------------------------------
__global__ void __launch_bounds__(256) edge_kernel(
    const float* __restrict__ P,
    const float* __restrict__ xyz,
    const float* __restrict__ rbf_mu,
    const float* __restrict__ rbf_sigma,
    const float* __restrict__ W_edge,
    const float* __restrict__ w_out,
    float* __restrict__ out,
    int L)
{
    const int i    = blockIdx.x;
    const int tid  = threadIdx.x;
    const int lane = tid & 31;
    const int wrp  = tid >> 5;

    __shared__ __align__(16) float sWeT[MM * KP];  // [m][k'] transposed, padded
    __shared__ float sWo[MM];
    __shared__ float sMu[KK], sI2[KK];
    __shared__ int   sList[LMAX];
    __shared__ float sPij[LMAX];
    __shared__ int   wsum[8];
    __shared__ float sred[8][3];

    // stage transposed W_edge: sWeT[m*36 + k] = W_edge[k*64 + m], zero pad
    for (int t = tid; t < MM * KP; t += 256) {
        int m = t / KP, k = t - m * KP;
        sWeT[t] = (k < KK + 2) ? W_edge[k * MM + m] : 0.f;
    }
    if (tid < MM) sWo[tid] = w_out[tid];
    if (tid < KK) {
        sMu[tid] = rbf_mu[tid];
        float s = rbf_sigma[tid];
        sI2[tid] = 1.f / (2.f * s * s);
    }
    const float xi = xyz[i * 3 + 0];
    const float yi = xyz[i * 3 + 1];
    const float zi = xyz[i * 3 + 2];

    // ---- deterministic edge compaction (each thread owns 4 consecutive j) ----
    const float4 p4 = reinterpret_cast<const float4*>(P + (size_t)i * L)[tid];
    float pv[4] = {p4.x, p4.y, p4.z, p4.w};
    int   myj[4]; float myp[4]; int c = 0;
    const int jb = tid * 4;
    #pragma unroll
    for (int r = 0; r < 4; r++) {
        int j = jb + r;
        bool bb = (j == i + 1);
        bool ct = (pv[r] > 0.2f) && (j > i + 2);
        if (bb || ct) { myj[c] = j; myp[c] = bb ? 1.f : pv[r]; c++; }
    }
    // intra-warp inclusive scan of counts
    int inc = c;
    #pragma unroll
    for (int off = 1; off < 32; off <<= 1) {
        int v = __shfl_up_sync(0xffffffffu, inc, off);
        if (lane >= off) inc += v;
    }
    if (lane == 31) wsum[wrp] = inc;
    __syncthreads();
    int offset = inc - c;
    int total  = 0;
    #pragma unroll
    for (int q = 0; q < 8; q++) {
        int wv = wsum[q];
        if (q < wrp) offset += wv;
        total += wv;
    }
    for (int t = 0; t < c; t++) { sList[offset + t] = myj[t]; sPij[offset + t] = myp[t]; }
    __syncthreads();

    // ---- per-edge fused compute ----
    float ax = 0.f, ay = 0.f, az = 0.f;
    for (int e = tid; e < total; e += 256) {
        int   j   = sList[e];
        float pij = sPij[e];
        float etype = (j == i + 1) ? 0.f : 1.f;
        float dx = xyz[j * 3 + 0] - xi;
        float dy = xyz[j * 3 + 1] - yi;
        float dz = xyz[j * 3 + 2] - zi;
        float d  = sqrtf(fmaf(dx, dx, fmaf(dy, dy, fmaf(dz, dz, 1e-12f))));

        float u[KP];
        u[0] = etype; u[1] = pij; u[34] = 0.f; u[35] = 0.f;
        #pragma unroll
        for (int k = 0; k < KK; k++) {
            float t = d - sMu[k];
            u[2 + k] = __expf(-t * t * sI2[k]);
        }

        float g = 0.f;
        const float4* nbj = reinterpret_cast<const float4*>(&g_nb[j * MM]);
        #pragma unroll 4
        for (int m = 0; m < MM; m += 4) {
            float4 nv = nbj[m >> 2];
            float a0 = nv.x, a1 = nv.y, a2 = nv.z, a3 = nv.w;
            const float4* w0 = reinterpret_cast<const float4*>(&sWeT[(m + 0) * KP]);
            const float4* w1 = reinterpret_cast<const float4*>(&sWeT[(m + 1) * KP]);
            const float4* w2 = reinterpret_cast<const float4*>(&sWeT[(m + 2) * KP]);
            const float4* w3 = reinterpret_cast<const float4*>(&sWeT[(m + 3) * KP]);
            #pragma unroll
            for (int q = 0; q < 9; q++) {
                float4 b0 = w0[q], b1 = w1[q], b2 = w2[q], b3 = w3[q];
                float ux = u[4 * q + 0], uy = u[4 * q + 1];
                float uz = u[4 * q + 2], uw = u[4 * q + 3];
                a0 = fmaf(b0.x, ux, fmaf(b0.y, uy, fmaf(b0.z, uz, fmaf(b0.w, uw, a0))));
                a1 = fmaf(b1.x, ux, fmaf(b1.y, uy, fmaf(b1.z, uz, fmaf(b1.w, uw, a1))));
                a2 = fmaf(b2.x, ux, fmaf(b2.y, uy, fmaf(b2.z, uz, fmaf(b2.w, uw, a2))));
                a3 = fmaf(b3.x, ux, fmaf(b3.y, uy, fmaf(b3.z, uz, fmaf(b3.w, uw, a3))));
            }
            g = fmaf(fmaxf(a0, 0.f), sWo[m + 0], g);
            g = fmaf(fmaxf(a1, 0.f), sWo[m + 1], g);
            g = fmaf(fmaxf(a2, 0.f), sWo[m + 2], g);
            g = fmaf(fmaxf(a3, 0.f), sWo[m + 3], g);
        }
        float gate = 1.f / (1.f + __expf(-g));
        ax = fmaf(gate, dx, ax);
        ay = fmaf(gate, dy, ay);
        az = fmaf(gate, dz, az);
    }

    // ---- block reduction (deterministic order) ----
    #pragma unroll
    for (int off = 16; off; off >>= 1) {
        ax += __shfl_down_sync(0xffffffffu, ax, off);
        ay += __shfl_down_sync(0xffffffffu, ay, off);
        az += __shfl_down_sync(0xffffffffu, az, off);
    }
    if (lane == 0) { sred[wrp][0] = ax; sred[wrp][1] = ay; sred[wrp][2] = az; }
    __syncthreads();
    if (tid == 0) {
        float tx = 0.f, ty = 0.f, tz = 0.f;
        #pragma unroll
        for (int q = 0; q < 8; q++) { tx += sred[q][0]; ty += sred[q][1]; tz += sred[q][2]; }
        out[i * 3 + 0] = xi + tx;
        out[i * 3 + 1] = yi + ty;
        out[i * 3 + 2] = zi + tz;
    }
}

// ---------------------------------------------------------------------------
extern "C" void kernel_launch(void* const* d_in, const int* in_sizes, int n_in,
                              void* d_out, int out_size)
{
    const float* S         = (const float*)d_in[0];
    const float* P         = (const float*)d_in[1];
    const float* xyz       = (const float*)d_in[2];
    const float* rbf_mu    = (const float*)d_in[3];
    const float* rbf_sigma = (const float*)d_in[4];
    const float* W_edge    = (const float*)d_in[5];
    const float* b_edge    = (const float*)d_in[6];
    const float* W_node    = (const float*)d_in[7];
    const float* w_out     = (const float*)d_in[8];
    float* out = (float*)d_out;

    int L = in_sizes[2] / 3;          // 1024
    int D = in_sizes[0] / L;          // 640

    node_proj_kernel<<<L / 4, 256>>>(S, W_node, b_edge, L, D);
    edge_kernel<<<L, 256>>>(P, xyz, rbf_mu, rbf_sigma, W_edge, w_out, out, L);
}

// round 2
// speedup vs baseline: 1.3508x; 1.3508x over previous
#include <cuda_runtime.h>

// Shapes fixed by the problem: L=1024, D=640, K=32, M=64
#define LMAX 1024
#define MM   64
#define KE   34    // e_scalar length (etype, pij, 32 rbf)
#define TE   128   // edges per tile

typedef unsigned long long u64;

// scratch: node projection + bias, 1024 x 64 fp32 = 256 KB (L2-resident)
__device__ float g_nb[LMAX * MM];

// ---- packed fp32x2 helpers (sm_103a dual-fp32 path) -----------------------
__device__ __forceinline__ u64 pack2(float lo, float hi) {
    u64 r; asm("mov.b64 %0, {%1, %2};" : "=l"(r) : "f"(lo), "f"(hi)); return r;
}
__device__ __forceinline__ u64 ffma2(u64 a, u64 b, u64 c) {
    u64 d; asm("fma.rn.f32x2 %0, %1, %2, %3;" : "=l"(d) : "l"(a), "l"(b), "l"(c));
    return d;
}
__device__ __forceinline__ float2 unpack2(u64 v) {
    unsigned lo, hi; asm("mov.b64 {%0, %1}, %2;" : "=r"(lo), "=r"(hi) : "l"(v));
    float2 f; f.x = __uint_as_float(lo); f.y = __uint_as_float(hi); return f;
}

// ---------------------------------------------------------------------------
// Kernel 1: nb[j,m] = sum_d S[j,d] * W_node[d,m] + b_edge[m]
// 128 blocks x 8 rows, 256 threads = 64 m x 4 row-slots (2 rows per thread)
// ---------------------------------------------------------------------------
__global__ void __launch_bounds__(256) node_proj_kernel(
    const float* __restrict__ S,
    const float* __restrict__ W_node,
    const float* __restrict__ b_edge,
    int L, int D)
{
    const int m  = threadIdx.x & 63;
    const int jr = threadIdx.x >> 6;     // 0..3
    const int j0 = blockIdx.x * 8;

    __shared__ float sS[8][64];
    __shared__ float sW[64][65];

    float a0 = 0.f, a1 = 0.f;
    for (int d0 = 0; d0 < D; d0 += 64) {
        sS[jr][m]     = S[(size_t)(j0 + jr) * D + d0 + m];
        sS[jr + 4][m] = S[(size_t)(j0 + jr + 4) * D + d0 + m];
        #pragma unroll
        for (int r = 0; r < 64; r += 4)
            sW[r + jr][m] = W_node[(size_t)(d0 + r + jr) * MM + m];
        __syncthreads();
        #pragma unroll
        for (int d = 0; d < 64; d++) {
            float w = sW[d][m];
            a0 = fmaf(sS[jr][d], w, a0);
            a1 = fmaf(sS[jr + 4][d], w, a1);
        }
        __syncthreads();
    }
    float b = b_edge[m];
    g_nb[(j0 + jr) * MM + m]     = a0 + b;
    g_nb[(j0 + jr + 4) * MM + m] = a1 + b;
}

// ---------------------------------------------------------------------------
// Kernel 2: grid 512, block 256; block b handles rows b and 1023-b (balance).
// Per row: compact edges, then tiles of 128 edges:
//   A) build u[34][128] in smem    B) register-blocked 4m x 8e FFMA2 GEMM
// ---------------------------------------------------------------------------
__global__ void __launch_bounds__(256, 3) edge_kernel(
    const float* __restrict__ P,
    const float* __restrict__ xyz,
    const float* __restrict__ rbf_mu,
    const float* __restrict__ rbf_sigma,
    const float* __restrict__ W_edge,
    const float* __restrict__ w_out,
    float* __restrict__ out,
    int L)
{
    __shared__ __align__(16) float sW[KE * MM];   // 8704 B, [k][m]
    __shared__ __align__(16) float sU[KE * TE];   // 17408 B, [k][e]
    __shared__ int   sList[LMAX];                 // 4 KB
    __shared__ float sPij[LMAX];                  // 4 KB
    __shared__ float sD[LMAX];                    // 4 KB
    __shared__ __align__(16) float sWo[MM];
    __shared__ float sMu[32], sI2[32];
    __shared__ int   wsum[8];
    __shared__ float sred[8][3];

    const int tid  = threadIdx.x;
    const int lane = tid & 31;
    const int wrp  = tid >> 5;
    const int mg   = tid & 15;   // owns m = mg*4 .. mg*4+3
    const int eg   = tid >> 4;   // owns edges eg*8 .. eg*8+7 of tile

    // one-time staging (W_edge is already [k][m] row-major)
    for (int t = tid; t < KE * MM; t += 256) sW[t] = W_edge[t];
    if (tid < MM) sWo[tid] = w_out[tid];
    if (tid < 32) {
        sMu[tid] = rbf_mu[tid];
        float s = rbf_sigma[tid];
        sI2[tid] = 1.f / (2.f * s * s);
    }

    for (int half = 0; half < 2; half++) {
        const int i = half ? (L - 1 - blockIdx.x) : blockIdx.x;
        __syncthreads();   // staging visible / smem reuse across rows

        const float xi = xyz[i * 3 + 0];
        const float yi = xyz[i * 3 + 1];
        const float zi = xyz[i * 3 + 2];

        // ---- deterministic compaction: thread owns 4 consecutive j ----
        const float4 p4 = reinterpret_cast<const float4*>(P + (size_t)i * L)[tid];
        float pv[4] = {p4.x, p4.y, p4.z, p4.w};
        int myj[4]; float myp[4]; int c = 0;
        const int jb = tid * 4;
        #pragma unroll
        for (int r = 0; r < 4; r++) {
            int j = jb + r;
            bool bb = (j == i + 1);
            bool ct = (pv[r] > 0.2f) && (j > i + 2);
            if (bb || ct) { myj[c] = j; myp[c] = bb ? 1.f : pv[r]; c++; }
        }
        int inc = c;
        #pragma unroll
        for (int off = 1; off < 32; off <<= 1) {
            int v = __shfl_up_sync(0xffffffffu, inc, off);
            if (lane >= off) inc += v;
        }
        if (lane == 31) wsum[wrp] = inc;
        __syncthreads();
        int offset = inc - c;
        int total  = 0;
        #pragma unroll
        for (int q = 0; q < 8; q++) {
            int wv = wsum[q];
            if (q < wrp) offset += wv;
            total += wv;
        }
        for (int t = 0; t < c; t++) { sList[offset + t] = myj[t]; sPij[offset + t] = myp[t]; }
        __syncthreads();

        const int ntiles = (total + TE - 1) / TE;

        // ---- per-edge meta (d) + pad tail slots ----
        for (int e = tid; e < ntiles * TE; e += 256) {
            if (e < total) {
                int j = sList[e];
                float dx = xyz[3 * j + 0] - xi;
                float dy = xyz[3 * j + 1] - yi;
                float dz = xyz[3 * j + 2] - zi;
                sD[e] = sqrtf(fmaf(dx, dx, fmaf(dy, dy, fmaf(dz, dz, 1e-12f))));
            } else {
                sList[e] = 0; sPij[e] = 0.f; sD[e] = 0.f;
            }
        }
        __syncthreads();

        float ax = 0.f, ay = 0.f, az = 0.f;

        for (int tb = 0; tb < ntiles; tb++) {
            const int base = tb * TE;

            // ---- phase A: u[k][e] for this tile (k uniform per warp) ----
            for (int v = tid; v < KE * TE; v += 256) {
                int k = v >> 7, e = v & 127;
                int geidx = base + e;
                float val;
                if (k == 0)      val = (sList[geidx] == i + 1) ? 0.f : 1.f;
                else if (k == 1) val = sPij[geidx];
                else {
                    float t = sD[geidx] - sMu[k - 2];
                    val = __expf(-t * t * sI2[k - 2]);
                }
                sU[v] = val;
            }
            __syncthreads();

            // ---- phase B: msg accumulation, 4 m x 8 e per thread ----
            const int eb = base + eg * 8;
            u64 acc[4][4];
            #pragma unroll
            for (int p = 0; p < 4; p++) {
                int ja = sList[eb + 2 * p], jb2 = sList[eb + 2 * p + 1];
                float4 n0 = *(const float4*)&g_nb[ja * MM + mg * 4];
                float4 n1 = *(const float4*)&g_nb[jb2 * MM + mg * 4];
                acc[0][p] = pack2(n0.x, n1.x);
                acc[1][p] = pack2(n0.y, n1.y);
                acc[2][p] = pack2(n0.z, n1.z);
                acc[3][p] = pack2(n0.w, n1.w);
            }
            #pragma unroll
            for (int k = 0; k < KE; k++) {
                float4 wv = *(const float4*)&sW[k * MM + mg * 4];
                u64 w0 = pack2(wv.x, wv.x), w1 = pack2(wv.y, wv.y);
                u64 w2 = pack2(wv.z, wv.z), w3 = pack2(wv.w, wv.w);
                const ulonglong2* up = (const ulonglong2*)&sU[k * TE + eg * 8];
                ulonglong2 ua = up[0], ub = up[1];
                acc[0][0] = ffma2(w0, ua.x, acc[0][0]);
                acc[1][0] = ffma2(w1, ua.x, acc[1][0]);
                acc[2][0] = ffma2(w2, ua.x, acc[2][0]);
                acc[3][0] = ffma2(w3, ua.x, acc[3][0]);
                acc[0][1] = ffma2(w0, ua.y, acc[0][1]);
                acc[1][1] = ffma2(w1, ua.y, acc[1][1]);
                acc[2][1] = ffma2(w2, ua.y, acc[2][1]);
                acc[3][1] = ffma2(w3, ua.y, acc[3][1]);
                acc[0][2] = ffma2(w0, ub.x, acc[0][2]);
                acc[1][2] = ffma2(w1, ub.x, acc[1][2]);
                acc[2][2] = ffma2(w2, ub.x, acc[2][2]);
                acc[3][2] = ffma2(w3, ub.x, acc[3][2]);
                acc[0][3] = ffma2(w0, ub.y, acc[0][3]);
                acc[1][3] = ffma2(w1, ub.y, acc[1][3]);
                acc[2][3] = ffma2(w2, ub.y, acc[2][3]);
                acc[3][3] = ffma2(w3, ub.y, acc[3][3]);
            }

            // ---- epilogue: relu . w_out, reduce over 16 mg lanes ----
            float4 wov = *(const float4*)&sWo[mg * 4];
            float ge[8];
            #pragma unroll
            for (int p = 0; p < 4; p++) {
                float2 a0 = unpack2(acc[0][p]), a1 = unpack2(acc[1][p]);
                float2 a2 = unpack2(acc[2][p]), a3 = unpack2(acc[3][p]);
                ge[2 * p] = fmaf(fmaxf(a0.x, 0.f), wov.x,
                            fmaf(fmaxf(a1.x, 0.f), wov.y,
                            fmaf(fmaxf(a2.x, 0.f), wov.z,
                                 fmaxf(a3.x, 0.f) * wov.w)));
                ge[2 * p + 1] = fmaf(fmaxf(a0.y, 0.f), wov.x,
                                fmaf(fmaxf(a1.y, 0.f), wov.y,
                                fmaf(fmaxf(a2.y, 0.f), wov.z,
                                     fmaxf(a3.y, 0.f) * wov.w)));
            }
            #pragma unroll
            for (int q = 0; q < 8; q++) {
                ge[q] += __shfl_xor_sync(0xffffffffu, ge[q], 1, 16);
                ge[q] += __shfl_xor_sync(0xffffffffu, ge[q], 2, 16);
                ge[q] += __shfl_xor_sync(0xffffffffu, ge[q], 4, 16);
                ge[q] += __shfl_xor_sync(0xffffffffu, ge[q], 8, 16);
            }
            int e = eb + mg;
            if (mg < 8 && e < total) {
                float gsel = ge[0];
                #pragma unroll
                for (int q = 1; q < 8; q++) if (mg == q) gsel = ge[q];
                float gate = 1.f / (1.f + __expf(-gsel));
                int j = sList[e];
                float dx = xyz[3 * j + 0] - xi;
                float dy = xyz[3 * j + 1] - yi;
                float dz = xyz[3 * j + 2] - zi;
                ax = fmaf(gate, dx, ax);
                ay = fmaf(gate, dy, ay);
                az = fmaf(gate, dz, az);
            }
            __syncthreads();   // sU reuse next tile
        }

        // ---- block reduction, deterministic order ----
        #pragma unroll
        for (int off = 16; off; off >>= 1) {
            ax += __shfl_down_sync(0xffffffffu, ax, off);
            ay += __shfl_down_sync(0xffffffffu, ay, off);
            az += __shfl_down_sync(0xffffffffu, az, off);
        }
        if (lane == 0) { sred[wrp][0] = ax; sred[wrp][1] = ay; sred[wrp][2] = az; }
        __syncthreads();
        if (tid == 0) {
            float tx = 0.f, ty = 0.f, tz = 0.f;
            #pragma unroll
            for (int q = 0; q < 8; q++) { tx += sred[q][0]; ty += sred[q][1]; tz += sred[q][2]; }
            out[i * 3 + 0] = xi + tx;
            out[i * 3 + 1] = yi + ty;
            out[i * 3 + 2] = zi + tz;
        }
    }
}

// ---------------------------------------------------------------------------
extern "C" void kernel_launch(void* const* d_in, const int* in_sizes, int n_in,
                              void* d_out, int out_size)
{
    const float* S         = (const float*)d_in[0];
    const float* P         = (const float*)d_in[1];
    const float* xyz       = (const float*)d_in[2];
    const float* rbf_mu    = (const float*)d_in[3];
    const float* rbf_sigma = (const float*)d_in[4];
    const float* W_edge    = (const float*)d_in[5];
    const float* b_edge    = (const float*)d_in[6];
    const float* W_node    = (const float*)d_in[7];
    const float* w_out     = (const float*)d_in[8];
    float* out = (float*)d_out;

    int L = in_sizes[2] / 3;          // 1024
    int D = in_sizes[0] / L;          // 640

    node_proj_kernel<<<L / 8, 256>>>(S, W_node, b_edge, L, D);
    edge_kernel<<<L / 2, 256>>>(P, xyz, rbf_mu, rbf_sigma, W_edge, w_out, out, L);
}